// round 1
// baseline (speedup 1.0000x reference)
#include <cuda_runtime.h>
#include <math.h>

#define NN   50000
#define NE   800000
#define FINC 128
#define EINC 16
#define HID  72
#define EPSV 1e-5f

// ---------------- device scratch (no allocations allowed) ----------------
__device__ float  g_deg [NN];
__device__ float  g_dinv[NN];
__device__ float  g_h   [NN*HID];   // pre-BN relu output of current layer
__device__ float  g_m   [NN*HID];   // h @ conv_w
__device__ float  g_acc [NN*HID];   // init hV + b, then scatter-accumulated
__device__ double g_bnsum[HID];
__device__ double g_bnsq [HID];
__device__ float  g_bna [HID];      // folded BN scale of the *previous* layer
__device__ float  g_bnb [HID];      // folded BN shift

// ---------------- init: zero deg, identity BN affine, zero stats ----------------
__global__ void k_init() {
    int t = blockIdx.x * blockDim.x + threadIdx.x;
    for (int i = t; i < NN; i += gridDim.x * blockDim.x) g_deg[i] = 0.f;
    if (t < HID) { g_bna[t] = 1.f; g_bnb[t] = 0.f; g_bnsum[t] = 0.0; g_bnsq[t] = 0.0; }
}

__global__ void k_deg(const int* __restrict__ ei) {
    int e = blockIdx.x * blockDim.x + threadIdx.x;
    if (e < NE) atomicAdd(&g_deg[ei[NE + e]], 1.f);
}

__global__ void k_dinv() {
    int i = blockIdx.x * blockDim.x + threadIdx.x;
    if (i < NN) { float d = g_deg[i]; g_dinv[i] = d > 0.f ? rsqrtf(d) : 0.f; }
}

// ---------------- h = relu(x @ W + b), [50000x128]@[128x72] ----------------
// 288 threads = 72 j x 4 node-groups, 4 nodes per thread -> 16 nodes/block
__global__ void k_nodelin(const float* __restrict__ x, const float* __restrict__ w,
                          const float* __restrict__ b) {
    __shared__ float Ws[FINC * HID];
    __shared__ float xs[16 * FINC];
    int tx = threadIdx.x;
    for (int i = tx; i < FINC * HID; i += 288) Ws[i] = w[i];
    int nb = blockIdx.x * 16;
    for (int i = tx; i < 16 * FINC; i += 288) xs[i] = x[nb * FINC + i];
    __syncthreads();
    int j = tx % HID, g = tx / HID;
    float bv = b[j];
    float a0 = bv, a1 = bv, a2 = bv, a3 = bv;
    const float* xr = &xs[g * 4 * FINC];
    #pragma unroll 8
    for (int k = 0; k < FINC; k++) {
        float wv = Ws[k * HID + j];
        a0 += xr[k] * wv;
        a1 += xr[FINC + k] * wv;
        a2 += xr[2 * FINC + k] * wv;
        a3 += xr[3 * FINC + k] * wv;
    }
    int n = nb + g * 4;
    g_h[(n + 0) * HID + j] = fmaxf(a0, 0.f);
    g_h[(n + 1) * HID + j] = fmaxf(a1, 0.f);
    g_h[(n + 2) * HID + j] = fmaxf(a2, 0.f);
    g_h[(n + 3) * HID + j] = fmaxf(a3, 0.f);
}

// ---------------- per layer: m = hb @ Ww ; acc = hb @ Wv + b ----------------
// hb = BN-affine(previous pre-activation) folded at load time.
__global__ void k_gemm2(const float* __restrict__ cw, const float* __restrict__ cv,
                        const float* __restrict__ cb, int layer) {
    __shared__ float Ww[HID * HID], Wv[HID * HID], hs[16 * HID];
    int tx = threadIdx.x;
    const float* cwl = cw + layer * HID * HID;
    const float* cvl = cv + layer * HID * HID;
    for (int i = tx; i < HID * HID; i += 288) { Ww[i] = cwl[i]; Wv[i] = cvl[i]; }
    int nb = blockIdx.x * 16;
    for (int i = tx; i < 16 * HID; i += 288) {
        int c = i % HID;
        hs[i] = g_h[nb * HID + i] * g_bna[c] + g_bnb[c];
    }
    __syncthreads();
    int j = tx % HID, g = tx / HID;
    float bv = cb[layer * HID + j];
    float m0 = 0, m1 = 0, m2 = 0, m3 = 0;
    float v0 = bv, v1 = bv, v2 = bv, v3 = bv;
    const float* hr = &hs[g * 4 * HID];
    #pragma unroll 8
    for (int k = 0; k < HID; k++) {
        float wm = Ww[k * HID + j], wv = Wv[k * HID + j];
        float h0 = hr[k], h1 = hr[HID + k], h2 = hr[2 * HID + k], h3 = hr[3 * HID + k];
        m0 += h0 * wm; v0 += h0 * wv;
        m1 += h1 * wm; v1 += h1 * wv;
        m2 += h2 * wm; v2 += h2 * wv;
        m3 += h3 * wm; v3 += h3 * wv;
    }
    int n = nb + g * 4;
    g_m[(n + 0) * HID + j] = m0; g_acc[(n + 0) * HID + j] = v0;
    g_m[(n + 1) * HID + j] = m1; g_acc[(n + 1) * HID + j] = v1;
    g_m[(n + 2) * HID + j] = m2; g_acc[(n + 2) * HID + j] = v2;
    g_m[(n + 3) * HID + j] = m3; g_acc[(n + 3) * HID + j] = v3;
}

// ---------------- edge scatter: acc[col] += norm * m[row] ----------------
__global__ void k_scatter(const int* __restrict__ ei) {
    int tx = threadIdx.x;
    int e = blockIdx.x * 4 + tx / HID;
    int j = tx % HID;
    int r = ei[e], c = ei[NE + e];
    float nrm = g_dinv[r] * g_dinv[c];
    atomicAdd(&g_acc[c * HID + j], nrm * g_m[r * HID + j]);
}

// ---------------- h = relu(acc); accumulate BN stats ----------------
__global__ void k_relustats() {
    __shared__ float ssum[HID], ssq[HID];
    int tx = threadIdx.x;
    if (tx < HID) { ssum[tx] = 0.f; ssq[tx] = 0.f; }
    __syncthreads();
    int j = tx % HID, g = tx / HID;
    int nb = blockIdx.x * 32 + g * 8;
    float s = 0.f, q = 0.f;
    for (int i = 0; i < 8; i++) {
        int n = nb + i;
        if (n < NN) {
            float v = g_acc[n * HID + j];
            v = fmaxf(v, 0.f);
            g_h[n * HID + j] = v;
            s += v; q += v * v;
        }
    }
    atomicAdd(&ssum[j], s);
    atomicAdd(&ssq[j], q);
    __syncthreads();
    if (tx < HID) {
        atomicAdd(&g_bnsum[tx], (double)ssum[tx]);
        atomicAdd(&g_bnsq[tx], (double)ssq[tx]);
    }
}

// ---------------- finalize BN: fold into (a,b) affine; reset stats ----------------
__global__ void k_bnfinal(const float* __restrict__ gamma, const float* __restrict__ beta,
                          int layer) {
    int t = threadIdx.x;
    if (t < HID) {
        double s = g_bnsum[t], q = g_bnsq[t];
        double mu = s / (double)NN;
        double var = q / (double)NN - mu * mu;
        float inv = rsqrtf((float)var + EPSV);
        float a = gamma[layer * HID + t] * inv;
        g_bna[t] = a;
        g_bnb[t] = beta[layer * HID + t] - (float)mu * a;
        g_bnsum[t] = 0.0; g_bnsq[t] = 0.0;
    }
}

// ---------------- fused edge head ----------------
// per 64-edge tile: gather feat[64][160] (h[row]|h[col]|edge_attr, BN folded)
//   z[:, :72]  = feat[:, :144] @ W1 + b1
//   z[:, 72:]  = feat[:,144:160] @ W2 + b2     (stored transposed zT[144][68pad])
//   out = tanh(z @ M1 + mb1) @ w2 + mb2
// 288 threads = 18 j-groups(4j) x 16 e-groups(4e); weights resident in smem.
#define ETILE 64
#define NT_E  288
__global__ void k_edge(const int* __restrict__ ei, const float* __restrict__ ea,
                       const float* __restrict__ W1, const float* __restrict__ b1,
                       const float* __restrict__ W2, const float* __restrict__ b2,
                       const float* __restrict__ M1, const float* __restrict__ mb1,
                       const float* __restrict__ w2, const float* __restrict__ mb2,
                       float* __restrict__ out) {
    extern __shared__ float sm[];
    float* sW1  = sm;                 // 144*72 = 10368
    float* sM1  = sW1 + 10368;        // 10368
    float* sW2  = sM1 + 10368;        // 16*72 = 1152
    float* sb1  = sW2 + 1152;         // 72
    float* sb2  = sb1 + 72;           // 72
    float* smb1 = sb2 + 72;           // 72
    float* sw2  = smb1 + 72;          // 72
    float* feat = sw2 + 72;           // 64*160 = 10240
    float* zT   = feat + 10240;       // 144*68 = 9792 (padded rows)
    float* sout = zT + 9792;          // 64
    int*   srow = (int*)(sout + 64);  // 64
    int*   scol = srow + 64;          // 64

    int tx = threadIdx.x;
    for (int i = tx; i < 10368; i += NT_E) { sW1[i] = W1[i]; sM1[i] = M1[i]; }
    for (int i = tx; i < 1152;  i += NT_E) sW2[i] = W2[i];
    if (tx < 72) { sb1[tx] = b1[tx]; sb2[tx] = b2[tx]; smb1[tx] = mb1[tx]; sw2[tx] = w2[tx]; }
    float mb2v = mb2[0];
    int jg = tx % 18, eg = tx / 18;
    int j0 = jg * 4, el0 = eg * 4;
    __syncthreads();

    for (int tile = blockIdx.x; tile < NE / ETILE; tile += gridDim.x) {
        int e0 = tile * ETILE;
        if (tx < ETILE) {
            srow[tx] = ei[e0 + tx];
            scol[tx] = ei[NE + e0 + tx];
            sout[tx] = 0.f;
        }
        __syncthreads();
        // gather node features with BN affine folded
        for (int idx = tx; idx < ETILE * 144; idx += NT_E) {
            int el = idx / 144, k = idx - el * 144;
            int node, c;
            if (k < 72) { node = srow[el]; c = k; } else { node = scol[el]; c = k - 72; }
            feat[el * 160 + k] = g_h[node * HID + c] * g_bna[c] + g_bnb[c];
        }
        for (int idx = tx; idx < ETILE * EINC; idx += NT_E) {
            int el = idx / EINC, k = idx - el * EINC;
            feat[el * 160 + 144 + k] = ea[(e0 + el) * EINC + k];
        }
        __syncthreads();

        // stage A: z1
        {
            float a[4][4];
            #pragma unroll
            for (int jj = 0; jj < 4; jj++) {
                float b = sb1[j0 + jj];
                a[0][jj] = b; a[1][jj] = b; a[2][jj] = b; a[3][jj] = b;
            }
            #pragma unroll 4
            for (int k = 0; k < 144; k++) {
                float4 w = *(const float4*)&sW1[k * 72 + j0];
                #pragma unroll
                for (int i = 0; i < 4; i++) {
                    float f = feat[(el0 + i) * 160 + k];
                    a[i][0] += f * w.x; a[i][1] += f * w.y;
                    a[i][2] += f * w.z; a[i][3] += f * w.w;
                }
            }
            #pragma unroll
            for (int jj = 0; jj < 4; jj++)
                *(float4*)&zT[(j0 + jj) * 68 + el0] =
                    make_float4(a[0][jj], a[1][jj], a[2][jj], a[3][jj]);
        }
        // stage A2: z2 (edge_attr path)
        {
            float a[4][4];
            #pragma unroll
            for (int jj = 0; jj < 4; jj++) {
                float b = sb2[j0 + jj];
                a[0][jj] = b; a[1][jj] = b; a[2][jj] = b; a[3][jj] = b;
            }
            #pragma unroll
            for (int k = 0; k < 16; k++) {
                float4 w = *(const float4*)&sW2[k * 72 + j0];
                #pragma unroll
                for (int i = 0; i < 4; i++) {
                    float f = feat[(el0 + i) * 160 + 144 + k];
                    a[i][0] += f * w.x; a[i][1] += f * w.y;
                    a[i][2] += f * w.z; a[i][3] += f * w.w;
                }
            }
            #pragma unroll
            for (int jj = 0; jj < 4; jj++)
                *(float4*)&zT[(72 + j0 + jj) * 68 + el0] =
                    make_float4(a[0][jj], a[1][jj], a[2][jj], a[3][jj]);
        }
        __syncthreads();

        // stage B: out = tanh(z @ M1 + mb1) . w2
        {
            float a[4][4];
            #pragma unroll
            for (int jj = 0; jj < 4; jj++) {
                float b = smb1[j0 + jj];
                a[0][jj] = b; a[1][jj] = b; a[2][jj] = b; a[3][jj] = b;
            }
            #pragma unroll 4
            for (int k = 0; k < 144; k++) {
                float4 z = *(const float4*)&zT[k * 68 + el0];
                float4 w = *(const float4*)&sM1[k * 72 + j0];
                a[0][0] += z.x * w.x; a[0][1] += z.x * w.y; a[0][2] += z.x * w.z; a[0][3] += z.x * w.w;
                a[1][0] += z.y * w.x; a[1][1] += z.y * w.y; a[1][2] += z.y * w.z; a[1][3] += z.y * w.w;
                a[2][0] += z.z * w.x; a[2][1] += z.z * w.y; a[2][2] += z.z * w.z; a[2][3] += z.z * w.w;
                a[3][0] += z.w * w.x; a[3][1] += z.w * w.y; a[3][2] += z.w * w.z; a[3][3] += z.w * w.w;
            }
            float p0 = 0.f, p1 = 0.f, p2 = 0.f, p3 = 0.f;
            #pragma unroll
            for (int jj = 0; jj < 4; jj++) {
                float wv = sw2[j0 + jj];
                p0 += tanhf(a[0][jj]) * wv;
                p1 += tanhf(a[1][jj]) * wv;
                p2 += tanhf(a[2][jj]) * wv;
                p3 += tanhf(a[3][jj]) * wv;
            }
            atomicAdd(&sout[el0 + 0], p0);
            atomicAdd(&sout[el0 + 1], p1);
            atomicAdd(&sout[el0 + 2], p2);
            atomicAdd(&sout[el0 + 3], p3);
        }
        __syncthreads();
        if (tx < ETILE) out[e0 + tx] = sout[tx] + mb2v;
        __syncthreads();
    }
}

// ---------------- launch ----------------
extern "C" void kernel_launch(void* const* d_in, const int* in_sizes, int n_in,
                              void* d_out, int out_size) {
    const float* x     = (const float*)d_in[0];
    const int*   ei    = (const int*)  d_in[1];
    const float* ea    = (const float*)d_in[2];
    const float* nlw   = (const float*)d_in[3];
    const float* nlb   = (const float*)d_in[4];
    const float* cw    = (const float*)d_in[5];
    const float* cv    = (const float*)d_in[6];
    const float* cb    = (const float*)d_in[7];
    const float* gamma = (const float*)d_in[8];
    const float* beta  = (const float*)d_in[9];
    const float* W1    = (const float*)d_in[10];
    const float* b1    = (const float*)d_in[11];
    const float* W2    = (const float*)d_in[12];
    const float* b2    = (const float*)d_in[13];
    const float* mw1   = (const float*)d_in[14];
    const float* mb1   = (const float*)d_in[15];
    const float* mw2   = (const float*)d_in[16];
    const float* mb2   = (const float*)d_in[17];
    float* out = (float*)d_out;

    cudaFuncSetAttribute(k_edge, cudaFuncAttributeMaxDynamicSharedMemorySize, 172 * 1024);

    k_init<<<64, 256>>>();
    k_deg<<<3125, 256>>>(ei);
    k_dinv<<<196, 256>>>();
    k_nodelin<<<3125, 288>>>(x, nlw, nlb);
    for (int t = 0; t < 3; t++) {
        k_gemm2<<<3125, 288>>>(cw, cv, cb, t);
        k_scatter<<<200000, 288>>>(ei);
        k_relustats<<<1563, 288>>>();
        k_bnfinal<<<1, 72>>>(gamma, beta, t);
    }
    k_edge<<<148, NT_E, 169600>>>(ei, ea, W1, b1, W2, b2, mw1, mb1, mw2, mb2, out);
}

// round 2
// speedup vs baseline: 1.0929x; 1.0929x over previous
#include <cuda_runtime.h>
#include <math.h>

#define NN   50000
#define NE   800000
#define FINC 128
#define EINC 16
#define HID  72
#define EPSV 1e-5f

// ---------------- device scratch (no allocations allowed) ----------------
__device__ int    g_degi[NN];
__device__ int    g_cnt [NN];
__device__ int    g_off [NN + 1];
__device__ int    g_esrc [NE];
__device__ float  g_enorm[NE];
__device__ float  g_dinv[NN];
__device__ float  g_h   [NN*HID];   // pre-BN relu output of current layer
__device__ float  g_m   [NN*HID];   // h @ conv_w
__device__ float  g_acc [NN*HID];   // hV + b (self term), read by aggregation
__device__ double g_bnsum[HID];
__device__ double g_bnsq [HID];
__device__ float  g_bna [HID];      // folded BN scale of the *previous* layer
__device__ float  g_bnb [HID];      // folded BN shift

// ---------------- init ----------------
__global__ void k_init() {
    int t = blockIdx.x * blockDim.x + threadIdx.x;
    for (int i = t; i < NN; i += gridDim.x * blockDim.x) { g_degi[i] = 0; g_cnt[i] = 0; }
    if (t < HID) { g_bna[t] = 1.f; g_bnb[t] = 0.f; g_bnsum[t] = 0.0; g_bnsq[t] = 0.0; }
}

__global__ void k_deg(const int* __restrict__ ei) {
    int e = blockIdx.x * blockDim.x + threadIdx.x;
    if (e < NE) atomicAdd(&g_degi[ei[NE + e]], 1);
}

// single-block exclusive prefix scan over 50000 degrees
__global__ void k_scan() {
    __shared__ int part[1024];
    int t = threadIdx.x;
    const int CH = (NN + 1023) / 1024;  // 49
    int base = t * CH;
    int s = 0;
    for (int i = 0; i < CH; i++) { int idx = base + i; if (idx < NN) s += g_degi[idx]; }
    part[t] = s;
    __syncthreads();
    for (int off = 1; off < 1024; off <<= 1) {
        int v = (t >= off) ? part[t - off] : 0;
        __syncthreads();
        part[t] += v;
        __syncthreads();
    }
    int run = (t == 0) ? 0 : part[t - 1];
    for (int i = 0; i < CH; i++) {
        int idx = base + i;
        if (idx < NN) { g_off[idx] = run; run += g_degi[idx]; }
    }
    if (t == 1023) g_off[NN] = NE;
}

__global__ void k_dinv() {
    int i = blockIdx.x * blockDim.x + threadIdx.x;
    if (i < NN) { int d = g_degi[i]; g_dinv[i] = d > 0 ? rsqrtf((float)d) : 0.f; }
}

// fill CSR slots: one atomic per edge; norm precomputed once for all layers
__global__ void k_fill(const int* __restrict__ ei) {
    int e = blockIdx.x * blockDim.x + threadIdx.x;
    if (e < NE) {
        int r = ei[e], c = ei[NE + e];
        int pos = g_off[c] + atomicAdd(&g_cnt[c], 1);
        g_esrc[pos]  = r;
        g_enorm[pos] = g_dinv[r] * g_dinv[c];
    }
}

// ---------------- h = relu(x @ W + b), [50000x128]@[128x72] ----------------
__global__ void k_nodelin(const float* __restrict__ x, const float* __restrict__ w,
                          const float* __restrict__ b) {
    __shared__ float Ws[FINC * HID];
    __shared__ float xs[16 * FINC];
    int tx = threadIdx.x;
    for (int i = tx; i < FINC * HID; i += 288) Ws[i] = w[i];
    int nb = blockIdx.x * 16;
    for (int i = tx; i < 16 * FINC; i += 288) xs[i] = x[nb * FINC + i];
    __syncthreads();
    int j = tx % HID, g = tx / HID;
    float bv = b[j];
    float a0 = bv, a1 = bv, a2 = bv, a3 = bv;
    const float* xr = &xs[g * 4 * FINC];
    #pragma unroll 8
    for (int k = 0; k < FINC; k++) {
        float wv = Ws[k * HID + j];
        a0 += xr[k] * wv;
        a1 += xr[FINC + k] * wv;
        a2 += xr[2 * FINC + k] * wv;
        a3 += xr[3 * FINC + k] * wv;
    }
    int n = nb + g * 4;
    g_h[(n + 0) * HID + j] = fmaxf(a0, 0.f);
    g_h[(n + 1) * HID + j] = fmaxf(a1, 0.f);
    g_h[(n + 2) * HID + j] = fmaxf(a2, 0.f);
    g_h[(n + 3) * HID + j] = fmaxf(a3, 0.f);
}

// ---------------- per layer: m = hb @ Ww ; acc = hb @ Wv + b ----------------
__global__ void k_gemm2(const float* __restrict__ cw, const float* __restrict__ cv,
                        const float* __restrict__ cb, int layer) {
    __shared__ float Ww[HID * HID], Wv[HID * HID], hs[16 * HID];
    int tx = threadIdx.x;
    const float* cwl = cw + layer * HID * HID;
    const float* cvl = cv + layer * HID * HID;
    for (int i = tx; i < HID * HID; i += 288) { Ww[i] = cwl[i]; Wv[i] = cvl[i]; }
    int nb = blockIdx.x * 16;
    for (int i = tx; i < 16 * HID; i += 288) {
        int c = i % HID;
        hs[i] = g_h[nb * HID + i] * g_bna[c] + g_bnb[c];
    }
    __syncthreads();
    int j = tx % HID, g = tx / HID;
    float bv = cb[layer * HID + j];
    float m0 = 0, m1 = 0, m2 = 0, m3 = 0;
    float v0 = bv, v1 = bv, v2 = bv, v3 = bv;
    const float* hr = &hs[g * 4 * HID];
    #pragma unroll 8
    for (int k = 0; k < HID; k++) {
        float wm = Ww[k * HID + j], wv = Wv[k * HID + j];
        float h0 = hr[k], h1 = hr[HID + k], h2 = hr[2 * HID + k], h3 = hr[3 * HID + k];
        m0 += h0 * wm; v0 += h0 * wv;
        m1 += h1 * wm; v1 += h1 * wv;
        m2 += h2 * wm; v2 += h2 * wv;
        m3 += h3 * wm; v3 += h3 * wv;
    }
    int n = nb + g * 4;
    g_m[(n + 0) * HID + j] = m0; g_acc[(n + 0) * HID + j] = v0;
    g_m[(n + 1) * HID + j] = m1; g_acc[(n + 1) * HID + j] = v1;
    g_m[(n + 2) * HID + j] = m2; g_acc[(n + 2) * HID + j] = v2;
    g_m[(n + 3) * HID + j] = m3; g_acc[(n + 3) * HID + j] = v3;
}

// ---------------- CSR aggregation + relu + BN stats, one warp per node ----------------
// lane covers j = lane, lane+32, (lane<8: lane+64). No global atomics for the sum.
#define NPW 4   // nodes per warp
__global__ void k_agg() {
    __shared__ float ssum[HID], ssq[HID];
    int tx = threadIdx.x;
    if (tx < HID) { ssum[tx] = 0.f; ssq[tx] = 0.f; }
    __syncthreads();
    int warp = tx / 32, lane = tx % 32;
    int nwarp = blockDim.x / 32;
    float ls0 = 0, lq0 = 0, ls1 = 0, lq1 = 0, ls2 = 0, lq2 = 0;
    for (int k = 0; k < NPW; k++) {
        int n = (blockIdx.x * nwarp + warp) * NPW + k;
        if (n >= NN) break;
        int s = g_off[n], e = g_off[n + 1];
        const float* ab = &g_acc[n * HID];
        float a0 = ab[lane];
        float a1 = ab[32 + lane];
        float a2 = (lane < 8) ? ab[64 + lane] : 0.f;
        for (int p = s; p < e; p++) {
            int src = g_esrc[p];
            float nrm = g_enorm[p];
            const float* mb = &g_m[src * HID];
            a0 += nrm * mb[lane];
            a1 += nrm * mb[32 + lane];
            if (lane < 8) a2 += nrm * mb[64 + lane];
        }
        a0 = fmaxf(a0, 0.f); a1 = fmaxf(a1, 0.f); a2 = fmaxf(a2, 0.f);
        float* hb = &g_h[n * HID];
        hb[lane] = a0;
        hb[32 + lane] = a1;
        if (lane < 8) hb[64 + lane] = a2;
        ls0 += a0; lq0 += a0 * a0;
        ls1 += a1; lq1 += a1 * a1;
        ls2 += a2; lq2 += a2 * a2;
    }
    atomicAdd(&ssum[lane], ls0);      atomicAdd(&ssq[lane], lq0);
    atomicAdd(&ssum[32 + lane], ls1); atomicAdd(&ssq[32 + lane], lq1);
    if (lane < 8) { atomicAdd(&ssum[64 + lane], ls2); atomicAdd(&ssq[64 + lane], lq2); }
    __syncthreads();
    if (tx < HID) {
        atomicAdd(&g_bnsum[tx], (double)ssum[tx]);
        atomicAdd(&g_bnsq[tx], (double)ssq[tx]);
    }
}

// ---------------- finalize BN: fold into (a,b) affine; reset stats ----------------
__global__ void k_bnfinal(const float* __restrict__ gamma, const float* __restrict__ beta,
                          int layer) {
    int t = threadIdx.x;
    if (t < HID) {
        double s = g_bnsum[t], q = g_bnsq[t];
        double mu = s / (double)NN;
        double var = q / (double)NN - mu * mu;
        float inv = rsqrtf((float)var + EPSV);
        float a = gamma[layer * HID + t] * inv;
        g_bna[t] = a;
        g_bnb[t] = beta[layer * HID + t] - (float)mu * a;
        g_bnsum[t] = 0.0; g_bnsq[t] = 0.0;
    }
}

// ---------------- fused edge head ----------------
#define ETILE 64
#define NT_E  288
__global__ void k_edge(const int* __restrict__ ei, const float* __restrict__ ea,
                       const float* __restrict__ W1, const float* __restrict__ b1,
                       const float* __restrict__ W2, const float* __restrict__ b2,
                       const float* __restrict__ M1, const float* __restrict__ mb1,
                       const float* __restrict__ w2, const float* __restrict__ mb2,
                       float* __restrict__ out) {
    extern __shared__ float sm[];
    float* sW1  = sm;                 // 144*72 = 10368
    float* sM1  = sW1 + 10368;        // 10368
    float* sW2  = sM1 + 10368;        // 16*72 = 1152
    float* sb1  = sW2 + 1152;         // 72
    float* sb2  = sb1 + 72;           // 72
    float* smb1 = sb2 + 72;           // 72
    float* sw2  = smb1 + 72;          // 72
    float* feat = sw2 + 72;           // 64*160 = 10240
    float* zT   = feat + 10240;       // 144*68 = 9792 (padded rows)
    float* sout = zT + 9792;          // 64
    int*   srow = (int*)(sout + 64);  // 64
    int*   scol = srow + 64;          // 64

    int tx = threadIdx.x;
    for (int i = tx; i < 10368; i += NT_E) { sW1[i] = W1[i]; sM1[i] = M1[i]; }
    for (int i = tx; i < 1152;  i += NT_E) sW2[i] = W2[i];
    if (tx < 72) { sb1[tx] = b1[tx]; sb2[tx] = b2[tx]; smb1[tx] = mb1[tx]; sw2[tx] = w2[tx]; }
    float mb2v = mb2[0];
    int jg = tx % 18, eg = tx / 18;
    int j0 = jg * 4, el0 = eg * 4;
    __syncthreads();

    for (int tile = blockIdx.x; tile < NE / ETILE; tile += gridDim.x) {
        int e0 = tile * ETILE;
        if (tx < ETILE) {
            srow[tx] = ei[e0 + tx];
            scol[tx] = ei[NE + e0 + tx];
            sout[tx] = 0.f;
        }
        __syncthreads();
        for (int idx = tx; idx < ETILE * 144; idx += NT_E) {
            int el = idx / 144, k = idx - el * 144;
            int node, c;
            if (k < 72) { node = srow[el]; c = k; } else { node = scol[el]; c = k - 72; }
            feat[el * 160 + k] = g_h[node * HID + c] * g_bna[c] + g_bnb[c];
        }
        for (int idx = tx; idx < ETILE * EINC; idx += NT_E) {
            int el = idx / EINC, k = idx - el * EINC;
            feat[el * 160 + 144 + k] = ea[(e0 + el) * EINC + k];
        }
        __syncthreads();

        // stage A: z1 = feat[:, :144] @ W1 + b1
        {
            float a[4][4];
            #pragma unroll
            for (int jj = 0; jj < 4; jj++) {
                float b = sb1[j0 + jj];
                a[0][jj] = b; a[1][jj] = b; a[2][jj] = b; a[3][jj] = b;
            }
            #pragma unroll 4
            for (int k = 0; k < 144; k++) {
                float4 w = *(const float4*)&sW1[k * 72 + j0];
                #pragma unroll
                for (int i = 0; i < 4; i++) {
                    float f = feat[(el0 + i) * 160 + k];
                    a[i][0] += f * w.x; a[i][1] += f * w.y;
                    a[i][2] += f * w.z; a[i][3] += f * w.w;
                }
            }
            #pragma unroll
            for (int jj = 0; jj < 4; jj++)
                *(float4*)&zT[(j0 + jj) * 68 + el0] =
                    make_float4(a[0][jj], a[1][jj], a[2][jj], a[3][jj]);
        }
        // stage A2: z2 = edge_attr @ W2 + b2
        {
            float a[4][4];
            #pragma unroll
            for (int jj = 0; jj < 4; jj++) {
                float b = sb2[j0 + jj];
                a[0][jj] = b; a[1][jj] = b; a[2][jj] = b; a[3][jj] = b;
            }
            #pragma unroll
            for (int k = 0; k < 16; k++) {
                float4 w = *(const float4*)&sW2[k * 72 + j0];
                #pragma unroll
                for (int i = 0; i < 4; i++) {
                    float f = feat[(el0 + i) * 160 + 144 + k];
                    a[i][0] += f * w.x; a[i][1] += f * w.y;
                    a[i][2] += f * w.z; a[i][3] += f * w.w;
                }
            }
            #pragma unroll
            for (int jj = 0; jj < 4; jj++)
                *(float4*)&zT[(72 + j0 + jj) * 68 + el0] =
                    make_float4(a[0][jj], a[1][jj], a[2][jj], a[3][jj]);
        }
        __syncthreads();

        // stage B: out = tanh(z @ M1 + mb1) . w2
        {
            float a[4][4];
            #pragma unroll
            for (int jj = 0; jj < 4; jj++) {
                float b = smb1[j0 + jj];
                a[0][jj] = b; a[1][jj] = b; a[2][jj] = b; a[3][jj] = b;
            }
            #pragma unroll 4
            for (int k = 0; k < 144; k++) {
                float4 z = *(const float4*)&zT[k * 68 + el0];
                float4 w = *(const float4*)&sM1[k * 72 + j0];
                a[0][0] += z.x * w.x; a[0][1] += z.x * w.y; a[0][2] += z.x * w.z; a[0][3] += z.x * w.w;
                a[1][0] += z.y * w.x; a[1][1] += z.y * w.y; a[1][2] += z.y * w.z; a[1][3] += z.y * w.w;
                a[2][0] += z.z * w.x; a[2][1] += z.z * w.y; a[2][2] += z.z * w.z; a[2][3] += z.z * w.w;
                a[3][0] += z.w * w.x; a[3][1] += z.w * w.y; a[3][2] += z.w * w.z; a[3][3] += z.w * w.w;
            }
            float p0 = 0.f, p1 = 0.f, p2 = 0.f, p3 = 0.f;
            #pragma unroll
            for (int jj = 0; jj < 4; jj++) {
                float wv = sw2[j0 + jj];
                p0 += tanhf(a[0][jj]) * wv;
                p1 += tanhf(a[1][jj]) * wv;
                p2 += tanhf(a[2][jj]) * wv;
                p3 += tanhf(a[3][jj]) * wv;
            }
            atomicAdd(&sout[el0 + 0], p0);
            atomicAdd(&sout[el0 + 1], p1);
            atomicAdd(&sout[el0 + 2], p2);
            atomicAdd(&sout[el0 + 3], p3);
        }
        __syncthreads();
        if (tx < ETILE) out[e0 + tx] = sout[tx] + mb2v;
        __syncthreads();
    }
}

// ---------------- launch ----------------
extern "C" void kernel_launch(void* const* d_in, const int* in_sizes, int n_in,
                              void* d_out, int out_size) {
    const float* x     = (const float*)d_in[0];
    const int*   ei    = (const int*)  d_in[1];
    const float* ea    = (const float*)d_in[2];
    const float* nlw   = (const float*)d_in[3];
    const float* nlb   = (const float*)d_in[4];
    const float* cw    = (const float*)d_in[5];
    const float* cv    = (const float*)d_in[6];
    const float* cb    = (const float*)d_in[7];
    const float* gamma = (const float*)d_in[8];
    const float* beta  = (const float*)d_in[9];
    const float* W1    = (const float*)d_in[10];
    const float* b1    = (const float*)d_in[11];
    const float* W2    = (const float*)d_in[12];
    const float* b2    = (const float*)d_in[13];
    const float* mw1   = (const float*)d_in[14];
    const float* mb1   = (const float*)d_in[15];
    const float* mw2   = (const float*)d_in[16];
    const float* mb2   = (const float*)d_in[17];
    float* out = (float*)d_out;

    cudaFuncSetAttribute(k_edge, cudaFuncAttributeMaxDynamicSharedMemorySize, 172 * 1024);

    k_init<<<64, 256>>>();
    k_deg<<<3125, 256>>>(ei);
    k_scan<<<1, 1024>>>();
    k_dinv<<<196, 256>>>();
    k_fill<<<3125, 256>>>(ei);
    k_nodelin<<<3125, 288>>>(x, nlw, nlb);
    for (int t = 0; t < 3; t++) {
        k_gemm2<<<3125, 288>>>(cw, cv, cb, t);
        k_agg<<<1563, 256>>>();
        k_bnfinal<<<1, 72>>>(gamma, beta, t);
    }
    k_edge<<<148, NT_E, 169600>>>(ei, ea, W1, b1, W2, b2, mw1, mb1, mw2, mb2, out);
}

// round 3
// speedup vs baseline: 2.8586x; 2.6155x over previous
#include <cuda_runtime.h>
#include <math.h>

#define NN   50000
#define NE   800000
#define FINC 128
#define EINC 16
#define HID  72
#define EPSV 1e-5f

// ---------------- device scratch ----------------
__device__ int    g_degi[NN];
__device__ int    g_cnt [NN];
__device__ int    g_off [NN + 1];
__device__ int    g_esrc [NE];
__device__ float  g_enorm[NE];
__device__ float  g_dinv[NN];
__device__ float  g_h   [NN*HID];   // pre-BN relu output of current layer
__device__ float  g_m   [NN*HID];   // h@Ww per layer; then u = hb@P
__device__ float  g_acc [NN*HID];   // hV + b per layer; then v = hb@Q
__device__ double g_bnsum[HID];
__device__ double g_bnsq [HID];
__device__ float  g_bna [HID];
__device__ float  g_bnb [HID];
__device__ float  g_zero[HID];
__device__ float  g_P[HID*HID];     // W1_top @ M1_top
__device__ float  g_Q[HID*HID];     // W1_bot @ M1_top
__device__ float  g_R[EINC*HID];    // W2 @ M1_bot
__device__ float  g_C[HID];         // b1@M1_top + b2@M1_bot + mb1

// ---------------- init ----------------
__global__ void k_init() {
    int t = blockIdx.x * blockDim.x + threadIdx.x;
    for (int i = t; i < NN; i += gridDim.x * blockDim.x) { g_degi[i] = 0; g_cnt[i] = 0; }
    if (t < HID) { g_bna[t] = 1.f; g_bnb[t] = 0.f; g_bnsum[t] = 0.0; g_bnsq[t] = 0.0; g_zero[t] = 0.f; }
}

__global__ void k_deg(const int* __restrict__ ei) {
    int e = blockIdx.x * blockDim.x + threadIdx.x;
    if (e < NE) atomicAdd(&g_degi[ei[NE + e]], 1);
}

// single-block exclusive prefix scan over NN degrees
__global__ void k_scan() {
    __shared__ int part[1024];
    int t = threadIdx.x;
    const int CH = (NN + 1023) / 1024;
    int base = t * CH;
    int s = 0;
    for (int i = 0; i < CH; i++) { int idx = base + i; if (idx < NN) s += g_degi[idx]; }
    part[t] = s;
    __syncthreads();
    for (int off = 1; off < 1024; off <<= 1) {
        int v = (t >= off) ? part[t - off] : 0;
        __syncthreads();
        part[t] += v;
        __syncthreads();
    }
    int run = (t == 0) ? 0 : part[t - 1];
    for (int i = 0; i < CH; i++) {
        int idx = base + i;
        if (idx < NN) { g_off[idx] = run; run += g_degi[idx]; }
    }
    if (t == 1023) g_off[NN] = NE;
}

__global__ void k_dinv() {
    int i = blockIdx.x * blockDim.x + threadIdx.x;
    if (i < NN) { int d = g_degi[i]; g_dinv[i] = d > 0 ? rsqrtf((float)d) : 0.f; }
}

__global__ void k_fill(const int* __restrict__ ei) {
    int e = blockIdx.x * blockDim.x + threadIdx.x;
    if (e < NE) {
        int r = ei[e], c = ei[NE + e];
        int pos = g_off[c] + atomicAdd(&g_cnt[c], 1);
        g_esrc[pos]  = r;
        g_enorm[pos] = g_dinv[r] * g_dinv[c];
    }
}

// ---------------- h = relu(x @ W + b) ----------------
__global__ void k_nodelin(const float* __restrict__ x, const float* __restrict__ w,
                          const float* __restrict__ b) {
    __shared__ float Ws[FINC * HID];
    __shared__ float xs[16 * FINC];
    int tx = threadIdx.x;
    for (int i = tx; i < FINC * HID; i += 288) Ws[i] = w[i];
    int nb = blockIdx.x * 16;
    for (int i = tx; i < 16 * FINC; i += 288) xs[i] = x[nb * FINC + i];
    __syncthreads();
    int j = tx % HID, g = tx / HID;
    float bv = b[j];
    float a0 = bv, a1 = bv, a2 = bv, a3 = bv;
    const float* xr = &xs[g * 4 * FINC];
    #pragma unroll 8
    for (int k = 0; k < FINC; k++) {
        float wv = Ws[k * HID + j];
        a0 += xr[k] * wv;
        a1 += xr[FINC + k] * wv;
        a2 += xr[2 * FINC + k] * wv;
        a3 += xr[3 * FINC + k] * wv;
    }
    int n = nb + g * 4;
    g_h[(n + 0) * HID + j] = fmaxf(a0, 0.f);
    g_h[(n + 1) * HID + j] = fmaxf(a1, 0.f);
    g_h[(n + 2) * HID + j] = fmaxf(a2, 0.f);
    g_h[(n + 3) * HID + j] = fmaxf(a3, 0.f);
}

// ---------------- dual GEMM body: g_m = hb@Ww ; g_acc = hb@Wv + bias ----------------
__device__ __forceinline__ void gemm2_body(const float* __restrict__ cwl,
                                           const float* __restrict__ cvl,
                                           const float* __restrict__ cbl) {
    __shared__ float Ww[HID * HID], Wv[HID * HID], hs[16 * HID];
    int tx = threadIdx.x;
    for (int i = tx; i < HID * HID; i += 288) { Ww[i] = cwl[i]; Wv[i] = cvl[i]; }
    int nb = blockIdx.x * 16;
    for (int i = tx; i < 16 * HID; i += 288) {
        int c = i % HID;
        hs[i] = g_h[nb * HID + i] * g_bna[c] + g_bnb[c];
    }
    __syncthreads();
    int j = tx % HID, g = tx / HID;
    float bv = cbl[j];
    float m0 = 0, m1 = 0, m2 = 0, m3 = 0;
    float v0 = bv, v1 = bv, v2 = bv, v3 = bv;
    const float* hr = &hs[g * 4 * HID];
    #pragma unroll 8
    for (int k = 0; k < HID; k++) {
        float wm = Ww[k * HID + j], wv = Wv[k * HID + j];
        float h0 = hr[k], h1 = hr[HID + k], h2 = hr[2 * HID + k], h3 = hr[3 * HID + k];
        m0 += h0 * wm; v0 += h0 * wv;
        m1 += h1 * wm; v1 += h1 * wv;
        m2 += h2 * wm; v2 += h2 * wv;
        m3 += h3 * wm; v3 += h3 * wv;
    }
    int n = nb + g * 4;
    g_m[(n + 0) * HID + j] = m0; g_acc[(n + 0) * HID + j] = v0;
    g_m[(n + 1) * HID + j] = m1; g_acc[(n + 1) * HID + j] = v1;
    g_m[(n + 2) * HID + j] = m2; g_acc[(n + 2) * HID + j] = v2;
    g_m[(n + 3) * HID + j] = m3; g_acc[(n + 3) * HID + j] = v3;
}

__global__ void k_gemm2(const float* __restrict__ cw, const float* __restrict__ cv,
                        const float* __restrict__ cb, int layer) {
    gemm2_body(cw + layer * HID * HID, cv + layer * HID * HID, cb + layer * HID);
}

// u = hb@P -> g_m ; v = hb@Q -> g_acc
__global__ void k_uv() { gemm2_body(g_P, g_Q, g_zero); }

// ---------------- CSR aggregation + relu + BN stats: one warp per node ----------------
__global__ void k_agg() {
    __shared__ float ssum[HID], ssq[HID];
    int tx = threadIdx.x;
    if (tx < HID) { ssum[tx] = 0.f; ssq[tx] = 0.f; }
    __syncthreads();
    int warp = tx >> 5, lane = tx & 31;
    int n = blockIdx.x * (blockDim.x >> 5) + warp;
    float ls0 = 0, lq0 = 0, ls1 = 0, lq1 = 0, ls2 = 0, lq2 = 0;
    if (n < NN) {
        int s = g_off[n], e = g_off[n + 1];
        const float* ab = &g_acc[n * HID];
        float a0 = ab[lane];
        float a1 = ab[32 + lane];
        float a2 = (lane < 8) ? ab[64 + lane] : 0.f;
        int p = s;
        for (; p + 3 < e; p += 4) {
            int s0 = g_esrc[p], s1 = g_esrc[p+1], s2 = g_esrc[p+2], s3 = g_esrc[p+3];
            float n0 = g_enorm[p], n1 = g_enorm[p+1], n2 = g_enorm[p+2], n3 = g_enorm[p+3];
            const float* m0 = &g_m[s0 * HID];
            const float* m1 = &g_m[s1 * HID];
            const float* m2 = &g_m[s2 * HID];
            const float* m3 = &g_m[s3 * HID];
            float x0 = m0[lane], x1 = m1[lane], x2 = m2[lane], x3 = m3[lane];
            float y0 = m0[32+lane], y1 = m1[32+lane], y2 = m2[32+lane], y3 = m3[32+lane];
            a0 += n0*x0 + n1*x1 + n2*x2 + n3*x3;
            a1 += n0*y0 + n1*y1 + n2*y2 + n3*y3;
            if (lane < 8) {
                a2 += n0*m0[64+lane] + n1*m1[64+lane] + n2*m2[64+lane] + n3*m3[64+lane];
            }
        }
        for (; p < e; p++) {
            int src = g_esrc[p];
            float nrm = g_enorm[p];
            const float* mb = &g_m[src * HID];
            a0 += nrm * mb[lane];
            a1 += nrm * mb[32 + lane];
            if (lane < 8) a2 += nrm * mb[64 + lane];
        }
        a0 = fmaxf(a0, 0.f); a1 = fmaxf(a1, 0.f); a2 = fmaxf(a2, 0.f);
        float* hb = &g_h[n * HID];
        hb[lane] = a0;
        hb[32 + lane] = a1;
        if (lane < 8) hb[64 + lane] = a2;
        ls0 = a0; lq0 = a0 * a0;
        ls1 = a1; lq1 = a1 * a1;
        ls2 = a2; lq2 = a2 * a2;
    }
    atomicAdd(&ssum[lane], ls0);      atomicAdd(&ssq[lane], lq0);
    atomicAdd(&ssum[32 + lane], ls1); atomicAdd(&ssq[32 + lane], lq1);
    if (lane < 8) { atomicAdd(&ssum[64 + lane], ls2); atomicAdd(&ssq[64 + lane], lq2); }
    __syncthreads();
    if (tx < HID) {
        atomicAdd(&g_bnsum[tx], (double)ssum[tx]);
        atomicAdd(&g_bnsq[tx], (double)ssq[tx]);
    }
}

__global__ void k_bnfinal(const float* __restrict__ gamma, const float* __restrict__ beta,
                          int layer) {
    int t = threadIdx.x;
    if (t < HID) {
        double s = g_bnsum[t], q = g_bnsq[t];
        double mu = s / (double)NN;
        double var = q / (double)NN - mu * mu;
        float inv = rsqrtf((float)var + EPSV);
        float a = gamma[layer * HID + t] * inv;
        g_bna[t] = a;
        g_bnb[t] = beta[layer * HID + t] - (float)mu * a;
        g_bnsum[t] = 0.0; g_bnsq[t] = 0.0;
    }
}

// ---------------- fold edge-head chain: P, Q, R, C ----------------
// P[i][j] = sum_k W1[i][k]     M1[k][j]       (i,k,j in [0,72))
// Q[i][j] = sum_k W1[72+i][k]  M1[k][j]
// R[a][j] = sum_k W2[a][k]     M1[72+k][j]    (a in [0,16))
// C[j]    = sum_k b1[k] M1[k][j] + sum_k b2[k] M1[72+k][j] + mb1[j]
__global__ void k_precomp(const float* __restrict__ W1, const float* __restrict__ W2,
                          const float* __restrict__ b1, const float* __restrict__ b2,
                          const float* __restrict__ M1, const float* __restrict__ mb1) {
    int b = blockIdx.x, j = threadIdx.x;
    if (b < 72) {
        float s = 0.f;
        for (int k = 0; k < 72; k++) s += W1[b * 72 + k] * M1[k * 72 + j];
        g_P[b * 72 + j] = s;
    } else if (b < 144) {
        int i = b - 72;
        float s = 0.f;
        for (int k = 0; k < 72; k++) s += W1[(72 + i) * 72 + k] * M1[k * 72 + j];
        g_Q[i * 72 + j] = s;
    } else if (b < 160) {
        int a = b - 144;
        float s = 0.f;
        for (int k = 0; k < 72; k++) s += W2[a * 72 + k] * M1[(72 + k) * 72 + j];
        g_R[a * 72 + j] = s;
    } else {
        float s = mb1[j];
        for (int k = 0; k < 72; k++) s += b1[k] * M1[k * 72 + j];
        for (int k = 0; k < 72; k++) s += b2[k] * M1[(72 + k) * 72 + j];
        g_C[j] = s;
    }
}

// ---------------- edge head: out[e] = tanh(u[row]+v[col]+ea@R+C) . w2 + mb2 ----------------
#define EB 256
__global__ void k_edge2(const int* __restrict__ ei, const float* __restrict__ ea,
                        const float* __restrict__ mw2, const float* __restrict__ mb2,
                        float* __restrict__ out) {
    __shared__ float sR[EINC * HID];   // 1152
    __shared__ float sw2[HID], sC[HID];
    int tx = threadIdx.x;
    for (int i = tx; i < EINC * HID; i += EB) sR[i] = g_R[i];
    if (tx < HID) { sw2[tx] = mw2[tx]; sC[tx] = g_C[tx]; }
    float mb2v = mb2[0];
    __syncthreads();
    int warp = tx >> 5, lane = tx & 31;
    int nw = gridDim.x * (EB >> 5);
    for (int e = blockIdx.x * (EB >> 5) + warp; e < NE; e += nw) {
        int r = ei[e], c = ei[NE + e];
        const float* up = &g_m[r * HID];
        const float* vp = &g_acc[c * HID];
        float p0 = up[lane]      + vp[lane]      + sC[lane];
        float p1 = up[32 + lane] + vp[32 + lane] + sC[32 + lane];
        float p2 = (lane < 8) ? up[64 + lane] + vp[64 + lane] + sC[64 + lane] : 0.f;
        float myea = ea[e * EINC + (lane & 15)];
        #pragma unroll
        for (int k = 0; k < EINC; k++) {
            float av = __shfl_sync(0xffffffffu, myea, k, 16);
            p0 += av * sR[k * HID + lane];
            p1 += av * sR[k * HID + 32 + lane];
            if (lane < 8) p2 += av * sR[k * HID + 64 + lane];
        }
        float t = tanhf(p0) * sw2[lane] + tanhf(p1) * sw2[32 + lane];
        if (lane < 8) t += tanhf(p2) * sw2[64 + lane];
        #pragma unroll
        for (int off = 16; off; off >>= 1) t += __shfl_xor_sync(0xffffffffu, t, off);
        if (lane == 0) out[e] = t + mb2v;
    }
}

// ---------------- launch ----------------
extern "C" void kernel_launch(void* const* d_in, const int* in_sizes, int n_in,
                              void* d_out, int out_size) {
    const float* x     = (const float*)d_in[0];
    const int*   ei    = (const int*)  d_in[1];
    const float* ea    = (const float*)d_in[2];
    const float* nlw   = (const float*)d_in[3];
    const float* nlb   = (const float*)d_in[4];
    const float* cw    = (const float*)d_in[5];
    const float* cv    = (const float*)d_in[6];
    const float* cb    = (const float*)d_in[7];
    const float* gamma = (const float*)d_in[8];
    const float* beta  = (const float*)d_in[9];
    const float* W1    = (const float*)d_in[10];
    const float* b1    = (const float*)d_in[11];
    const float* W2    = (const float*)d_in[12];
    const float* b2    = (const float*)d_in[13];
    const float* mw1   = (const float*)d_in[14];
    const float* mb1   = (const float*)d_in[15];
    const float* mw2   = (const float*)d_in[16];
    const float* mb2   = (const float*)d_in[17];
    float* out = (float*)d_out;

    k_init<<<64, 256>>>();
    k_deg<<<3125, 256>>>(ei);
    k_scan<<<1, 1024>>>();
    k_dinv<<<196, 256>>>();
    k_fill<<<3125, 256>>>(ei);
    k_nodelin<<<3125, 288>>>(x, nlw, nlb);
    for (int t = 0; t < 3; t++) {
        k_gemm2<<<3125, 288>>>(cw, cv, cb, t);
        k_agg<<<6250, 256>>>();
        k_bnfinal<<<1, 72>>>(gamma, beta, t);
    }
    k_precomp<<<161, 72>>>(W1, W2, b1, b2, mw1, mb1);
    k_uv<<<3125, 288>>>();
    k_edge2<<<1480, EB>>>(ei, ea, mw2, mb2, out);
}

// round 4
// speedup vs baseline: 3.3030x; 1.1555x over previous
#include <cuda_runtime.h>
#include <math.h>

#define NN   50000
#define NE   800000
#define FINC 128
#define EINC 16
#define HID  72
#define EPSV 1e-5f

// ---------------- device scratch ----------------
__device__ int    g_degi[NN];
__device__ int    g_cnt [NN];
__device__ int    g_off [NN + 1];
__device__ int    g_bsum[256];
__device__ int    g_boff[256];
__device__ int    g_esrc [NE];
__device__ float  g_enorm[NE];
__device__ float  g_dinv[NN];
__device__ float  g_h   [NN*HID];
__device__ float  g_m   [NN*HID];   // h@Ww per layer; then u = hb@P
__device__ float  g_acc [NN*HID];   // hV + b per layer; then v = hb@Q
__device__ double g_bnsum[HID];
__device__ double g_bnsq [HID];
__device__ float  g_bna [HID];
__device__ float  g_bnb [HID];
__device__ float  g_zero[HID];
__device__ float  g_P[HID*HID];
__device__ float  g_Q[HID*HID];
__device__ float  g_R[EINC*HID];
__device__ float  g_C[HID];
__device__ float  g_probe_out[NE];  // probe sink

// ---------------- init ----------------
__global__ void k_init() {
    int t = blockIdx.x * blockDim.x + threadIdx.x;
    for (int i = t; i < NN; i += gridDim.x * blockDim.x) { g_degi[i] = 0; g_cnt[i] = 0; }
    if (t < HID) { g_bna[t] = 1.f; g_bnb[t] = 0.f; g_bnsum[t] = 0.0; g_bnsq[t] = 0.0; g_zero[t] = 0.f; }
}

__global__ void k_deg(const int* __restrict__ ei) {
    int e = blockIdx.x * blockDim.x + threadIdx.x;
    if (e < NE) atomicAdd(&g_degi[ei[NE + e]], 1);
}

// ---------------- 3-phase parallel exclusive scan over degrees ----------------
#define SCB 196   // blocks of 256
__global__ void k_scan1() {
    __shared__ int s[256];
    int t = threadIdx.x, i = blockIdx.x * 256 + t;
    int v = (i < NN) ? g_degi[i] : 0;
    s[t] = v;
    __syncthreads();
    for (int off = 128; off; off >>= 1) {
        if (t < off) s[t] += s[t + off];
        __syncthreads();
    }
    if (t == 0) g_bsum[blockIdx.x] = s[0];
}

__global__ void k_scan2() {
    __shared__ int s[256];
    int t = threadIdx.x;
    s[t] = (t < SCB) ? g_bsum[t] : 0;
    __syncthreads();
    for (int off = 1; off < 256; off <<= 1) {
        int u = (t >= off) ? s[t - off] : 0;
        __syncthreads();
        s[t] += u;
        __syncthreads();
    }
    g_boff[t] = (t == 0) ? 0 : s[t - 1];
    if (t == 0) g_off[NN] = NE;
}

__global__ void k_scan3() {
    __shared__ int s[256];
    int t = threadIdx.x, i = blockIdx.x * 256 + t;
    int d = (i < NN) ? g_degi[i] : 0;
    s[t] = d;
    __syncthreads();
    for (int off = 1; off < 256; off <<= 1) {
        int u = (t >= off) ? s[t - off] : 0;
        __syncthreads();
        s[t] += u;
        __syncthreads();
    }
    if (i < NN) {
        g_off[i] = g_boff[blockIdx.x] + s[t] - d;
        g_dinv[i] = d > 0 ? rsqrtf((float)d) : 0.f;
    }
}

__global__ void k_fill(const int* __restrict__ ei) {
    int e = blockIdx.x * blockDim.x + threadIdx.x;
    if (e < NE) {
        int r = ei[e], c = ei[NE + e];
        int pos = g_off[c] + atomicAdd(&g_cnt[c], 1);
        g_esrc[pos]  = r;
        g_enorm[pos] = g_dinv[r] * g_dinv[c];
    }
}

// ---------------- h = relu(x @ W + b): 64 nodes/block, 4n x 4j per thread ----------------
#define GN 64
__global__ void k_nodelin(const float* __restrict__ x, const float* __restrict__ w,
                          const float* __restrict__ b) {
    extern __shared__ float sm[];
    float* Ws = sm;               // 128*72
    float* xs = Ws + FINC * HID;  // 64*129 padded
    int tx = threadIdx.x;         // 288
    for (int i = tx; i < FINC * HID; i += 288) Ws[i] = w[i];
    int nb = blockIdx.x * GN;
    for (int i = tx; i < GN * FINC; i += 288) {
        int n = i >> 7, c = i & 127;
        xs[n * 129 + c] = (nb + n < NN) ? x[(nb + n) * FINC + c] : 0.f;
    }
    __syncthreads();
    int ng = tx & 15, jg = tx >> 4;
    int j0 = jg * 4, n0 = ng * 4;
    float4 bv = *(const float4*)&b[j0];
    float4 a0 = bv, a1 = bv, a2 = bv, a3 = bv;
    #pragma unroll 4
    for (int k = 0; k < FINC; k++) {
        float4 wv = *(const float4*)&Ws[k * HID + j0];
        float h0 = xs[(n0 + 0) * 129 + k];
        float h1 = xs[(n0 + 1) * 129 + k];
        float h2 = xs[(n0 + 2) * 129 + k];
        float h3 = xs[(n0 + 3) * 129 + k];
        a0.x += h0 * wv.x; a0.y += h0 * wv.y; a0.z += h0 * wv.z; a0.w += h0 * wv.w;
        a1.x += h1 * wv.x; a1.y += h1 * wv.y; a1.z += h1 * wv.z; a1.w += h1 * wv.w;
        a2.x += h2 * wv.x; a2.y += h2 * wv.y; a2.z += h2 * wv.z; a2.w += h2 * wv.w;
        a3.x += h3 * wv.x; a3.y += h3 * wv.y; a3.z += h3 * wv.z; a3.w += h3 * wv.w;
    }
    float4 r[4] = {a0, a1, a2, a3};
    #pragma unroll
    for (int i = 0; i < 4; i++) {
        int n = nb + n0 + i;
        if (n < NN) {
            float4 v = r[i];
            v.x = fmaxf(v.x, 0.f); v.y = fmaxf(v.y, 0.f);
            v.z = fmaxf(v.z, 0.f); v.w = fmaxf(v.w, 0.f);
            *(float4*)&g_h[n * HID + j0] = v;
        }
    }
}

// ---------------- dual GEMM: g_m = hb@Ww ; g_acc = hb@Wv + bias ----------------
__device__ __forceinline__ void gemm2_body(const float* __restrict__ cwl,
                                           const float* __restrict__ cvl,
                                           const float* __restrict__ cbl) {
    extern __shared__ float sm[];
    float* Ww = sm;                // 72*72
    float* Wv = Ww + HID * HID;    // 72*72
    float* hs = Wv + HID * HID;    // 64*73 padded
    int tx = threadIdx.x;          // 288
    for (int i = tx; i < HID * HID; i += 288) { Ww[i] = cwl[i]; Wv[i] = cvl[i]; }
    int nb = blockIdx.x * GN;
    for (int i = tx; i < GN * HID; i += 288) {
        int n = i / HID, c = i - n * HID;
        hs[n * 73 + c] = (nb + n < NN) ? g_h[(nb + n) * HID + c] * g_bna[c] + g_bnb[c] : 0.f;
    }
    __syncthreads();
    int ng = tx & 15, jg = tx >> 4;
    int j0 = jg * 4, n0 = ng * 4;
    float4 bv = *(const float4*)&cbl[j0];
    float4 w0 = {0,0,0,0}, w1 = w0, w2 = w0, w3 = w0;
    float4 v0 = bv, v1 = bv, v2 = bv, v3 = bv;
    #pragma unroll 4
    for (int k = 0; k < HID; k++) {
        float4 ww = *(const float4*)&Ww[k * HID + j0];
        float4 wv = *(const float4*)&Wv[k * HID + j0];
        float h0 = hs[(n0 + 0) * 73 + k];
        float h1 = hs[(n0 + 1) * 73 + k];
        float h2 = hs[(n0 + 2) * 73 + k];
        float h3 = hs[(n0 + 3) * 73 + k];
        w0.x += h0 * ww.x; w0.y += h0 * ww.y; w0.z += h0 * ww.z; w0.w += h0 * ww.w;
        v0.x += h0 * wv.x; v0.y += h0 * wv.y; v0.z += h0 * wv.z; v0.w += h0 * wv.w;
        w1.x += h1 * ww.x; w1.y += h1 * ww.y; w1.z += h1 * ww.z; w1.w += h1 * ww.w;
        v1.x += h1 * wv.x; v1.y += h1 * wv.y; v1.z += h1 * wv.z; v1.w += h1 * wv.w;
        w2.x += h2 * ww.x; w2.y += h2 * ww.y; w2.z += h2 * ww.z; w2.w += h2 * ww.w;
        v2.x += h2 * wv.x; v2.y += h2 * wv.y; v2.z += h2 * wv.z; v2.w += h2 * wv.w;
        w3.x += h3 * ww.x; w3.y += h3 * ww.y; w3.z += h3 * ww.z; w3.w += h3 * ww.w;
        v3.x += h3 * wv.x; v3.y += h3 * wv.y; v3.z += h3 * wv.z; v3.w += h3 * wv.w;
    }
    float4 rw[4] = {w0, w1, w2, w3};
    float4 rv[4] = {v0, v1, v2, v3};
    #pragma unroll
    for (int i = 0; i < 4; i++) {
        int n = nb + n0 + i;
        if (n < NN) {
            *(float4*)&g_m  [n * HID + j0] = rw[i];
            *(float4*)&g_acc[n * HID + j0] = rv[i];
        }
    }
}

__global__ void k_gemm2(const float* __restrict__ cw, const float* __restrict__ cv,
                        const float* __restrict__ cb, int layer) {
    gemm2_body(cw + layer * HID * HID, cv + layer * HID * HID, cb + layer * HID);
}

__global__ void k_uv() { gemm2_body(g_P, g_Q, g_zero); }

// ---------------- CSR aggregation + relu + BN stats: one warp per node ----------------
__global__ void k_agg() {
    __shared__ float ssum[HID], ssq[HID];
    int tx = threadIdx.x;
    if (tx < HID) { ssum[tx] = 0.f; ssq[tx] = 0.f; }
    __syncthreads();
    int warp = tx >> 5, lane = tx & 31;
    int n = blockIdx.x * (blockDim.x >> 5) + warp;
    float ls0 = 0, lq0 = 0, ls1 = 0, lq1 = 0, ls2 = 0, lq2 = 0;
    if (n < NN) {
        int s = g_off[n], e = g_off[n + 1];
        const float* ab = &g_acc[n * HID];
        float a0 = ab[lane];
        float a1 = ab[32 + lane];
        float a2 = (lane < 8) ? ab[64 + lane] : 0.f;
        int p = s;
        for (; p + 3 < e; p += 4) {
            int s0 = g_esrc[p], s1 = g_esrc[p+1], s2 = g_esrc[p+2], s3 = g_esrc[p+3];
            float n0 = g_enorm[p], n1 = g_enorm[p+1], n2 = g_enorm[p+2], n3 = g_enorm[p+3];
            const float* m0 = &g_m[s0 * HID];
            const float* m1 = &g_m[s1 * HID];
            const float* m2 = &g_m[s2 * HID];
            const float* m3 = &g_m[s3 * HID];
            a0 += n0*m0[lane] + n1*m1[lane] + n2*m2[lane] + n3*m3[lane];
            a1 += n0*m0[32+lane] + n1*m1[32+lane] + n2*m2[32+lane] + n3*m3[32+lane];
            if (lane < 8)
                a2 += n0*m0[64+lane] + n1*m1[64+lane] + n2*m2[64+lane] + n3*m3[64+lane];
        }
        for (; p < e; p++) {
            int src = g_esrc[p];
            float nrm = g_enorm[p];
            const float* mb = &g_m[src * HID];
            a0 += nrm * mb[lane];
            a1 += nrm * mb[32 + lane];
            if (lane < 8) a2 += nrm * mb[64 + lane];
        }
        a0 = fmaxf(a0, 0.f); a1 = fmaxf(a1, 0.f); a2 = fmaxf(a2, 0.f);
        float* hb = &g_h[n * HID];
        hb[lane] = a0;
        hb[32 + lane] = a1;
        if (lane < 8) hb[64 + lane] = a2;
        ls0 = a0; lq0 = a0 * a0;
        ls1 = a1; lq1 = a1 * a1;
        ls2 = a2; lq2 = a2 * a2;
    }
    atomicAdd(&ssum[lane], ls0);      atomicAdd(&ssq[lane], lq0);
    atomicAdd(&ssum[32 + lane], ls1); atomicAdd(&ssq[32 + lane], lq1);
    if (lane < 8) { atomicAdd(&ssum[64 + lane], ls2); atomicAdd(&ssq[64 + lane], lq2); }
    __syncthreads();
    if (tx < HID) {
        atomicAdd(&g_bnsum[tx], (double)ssum[tx]);
        atomicAdd(&g_bnsq[tx], (double)ssq[tx]);
    }
}

__global__ void k_bnfinal(const float* __restrict__ gamma, const float* __restrict__ beta,
                          int layer) {
    int t = threadIdx.x;
    if (t < HID) {
        double s = g_bnsum[t], q = g_bnsq[t];
        double mu = s / (double)NN;
        double var = q / (double)NN - mu * mu;
        float inv = rsqrtf((float)var + EPSV);
        float a = gamma[layer * HID + t] * inv;
        g_bna[t] = a;
        g_bnb[t] = beta[layer * HID + t] - (float)mu * a;
        g_bnsum[t] = 0.0; g_bnsq[t] = 0.0;
    }
}

// ---------------- fold edge-head chain: P, Q, R, C ----------------
__global__ void k_precomp(const float* __restrict__ W1, const float* __restrict__ W2,
                          const float* __restrict__ b1, const float* __restrict__ b2,
                          const float* __restrict__ M1, const float* __restrict__ mb1) {
    int b = blockIdx.x, j = threadIdx.x;
    if (b < 72) {
        float s = 0.f;
        for (int k = 0; k < 72; k++) s += W1[b * 72 + k] * M1[k * 72 + j];
        g_P[b * 72 + j] = s;
    } else if (b < 144) {
        int i = b - 72;
        float s = 0.f;
        for (int k = 0; k < 72; k++) s += W1[(72 + i) * 72 + k] * M1[k * 72 + j];
        g_Q[i * 72 + j] = s;
    } else if (b < 160) {
        int a = b - 144;
        float s = 0.f;
        for (int k = 0; k < 72; k++) s += W2[a * 72 + k] * M1[(72 + k) * 72 + j];
        g_R[a * 72 + j] = s;
    } else {
        float s = mb1[j];
        for (int k = 0; k < 72; k++) s += b1[k] * M1[k * 72 + j];
        for (int k = 0; k < 72; k++) s += b2[k] * M1[(72 + k) * 72 + j];
        g_C[j] = s;
    }
}

// ---------------- edge head: 2 edges per warp, 16 lanes each ----------------
#define EB 256
__device__ __forceinline__ void edge_body(const int* __restrict__ ei,
                                          const float* __restrict__ ea,
                                          const float* __restrict__ mw2,
                                          const float* __restrict__ mb2,
                                          float* __restrict__ out, int ne) {
    __shared__ float sR[EINC * HID];
    __shared__ float sw2[HID], sC[HID];
    int tx = threadIdx.x;
    for (int i = tx; i < EINC * HID; i += EB) sR[i] = g_R[i];
    if (tx < HID) { sw2[tx] = mw2[tx]; sC[tx] = g_C[tx]; }
    float mb2v = mb2[0];
    __syncthreads();
    int warp = tx >> 5, lane = tx & 31;
    int hl = lane & 15, side = lane >> 4;
    int nwp = gridDim.x * (EB >> 5);
    for (int p = blockIdx.x * (EB >> 5) + warp; p < (ne >> 1); p += nwp) {
        int e = p * 2 + side;
        int r = ei[e], c = ei[NE + e];
        const float* up = &g_m[r * HID];
        const float* vp = &g_acc[c * HID];
        float p0 = up[hl]      + vp[hl]      + sC[hl];
        float p1 = up[16 + hl] + vp[16 + hl] + sC[16 + hl];
        float p2 = up[32 + hl] + vp[32 + hl] + sC[32 + hl];
        float p3 = up[48 + hl] + vp[48 + hl] + sC[48 + hl];
        float p4 = (hl < 8) ? up[64 + hl] + vp[64 + hl] + sC[64 + hl] : 0.f;
        float myea = ea[e * EINC + hl];
        #pragma unroll
        for (int k = 0; k < EINC; k++) {
            float av = __shfl_sync(0xffffffffu, myea, k, 16);
            p0 += av * sR[k * HID + hl];
            p1 += av * sR[k * HID + 16 + hl];
            p2 += av * sR[k * HID + 32 + hl];
            p3 += av * sR[k * HID + 48 + hl];
            if (hl < 8) p4 += av * sR[k * HID + 64 + hl];
        }
        float t = tanhf(p0) * sw2[hl] + tanhf(p1) * sw2[16 + hl]
                + tanhf(p2) * sw2[32 + hl] + tanhf(p3) * sw2[48 + hl];
        if (hl < 8) t += tanhf(p4) * sw2[64 + hl];
        #pragma unroll
        for (int off = 8; off; off >>= 1) t += __shfl_xor_sync(0xffffffffu, t, off, 16);
        if (hl == 0) out[e] = t + mb2v;
    }
}

__global__ void k_edge2(const int* __restrict__ ei, const float* __restrict__ ea,
                        const float* __restrict__ mw2, const float* __restrict__ mb2,
                        float* __restrict__ out) {
    edge_body(ei, ea, mw2, mb2, out, NE);
}

// probe: identical code path over NE/4 edges, sinks to scratch (launch #4 -> ncu)
__global__ void k_edge2_probe(const int* __restrict__ ei, const float* __restrict__ ea,
                              const float* __restrict__ mw2, const float* __restrict__ mb2) {
    edge_body(ei, ea, mw2, mb2, g_probe_out, NE / 4);
}

// ---------------- launch ----------------
extern "C" void kernel_launch(void* const* d_in, const int* in_sizes, int n_in,
                              void* d_out, int out_size) {
    const float* x     = (const float*)d_in[0];
    const int*   ei    = (const int*)  d_in[1];
    const float* ea    = (const float*)d_in[2];
    const float* nlw   = (const float*)d_in[3];
    const float* nlb   = (const float*)d_in[4];
    const float* cw    = (const float*)d_in[5];
    const float* cv    = (const float*)d_in[6];
    const float* cb    = (const float*)d_in[7];
    const float* gamma = (const float*)d_in[8];
    const float* beta  = (const float*)d_in[9];
    const float* W1    = (const float*)d_in[10];
    const float* b1    = (const float*)d_in[11];
    const float* W2    = (const float*)d_in[12];
    const float* b2    = (const float*)d_in[13];
    const float* mw1   = (const float*)d_in[14];
    const float* mb1   = (const float*)d_in[15];
    const float* mw2   = (const float*)d_in[16];
    const float* mb2   = (const float*)d_in[17];
    float* out = (float*)d_out;

    const int SM_NL = (FINC * HID + GN * 129) * 4;            // nodelin
    const int SM_G2 = (2 * HID * HID + GN * 73) * 4;          // gemm2 / uv
    cudaFuncSetAttribute(k_nodelin, cudaFuncAttributeMaxDynamicSharedMemorySize, SM_NL);
    cudaFuncSetAttribute(k_gemm2,   cudaFuncAttributeMaxDynamicSharedMemorySize, SM_G2);
    cudaFuncSetAttribute(k_uv,      cudaFuncAttributeMaxDynamicSharedMemorySize, SM_G2);

    k_init<<<64, 256>>>();                               // 1
    k_deg<<<3125, 256>>>(ei);                            // 2
    k_scan1<<<SCB, 256>>>();                             // 3
    k_edge2_probe<<<1480, EB>>>(ei, ea, mw2, mb2);       // 4  <- ncu capture slot
    k_scan2<<<1, 256>>>();                               // 5
    k_scan3<<<SCB, 256>>>();                             // 6
    k_fill<<<3125, 256>>>(ei);                           // 7
    k_nodelin<<<782, 288, SM_NL>>>(x, nlw, nlb);         // 8
    for (int t = 0; t < 3; t++) {
        k_gemm2<<<782, 288, SM_G2>>>(cw, cv, cb, t);
        k_agg<<<6250, 256>>>();
        k_bnfinal<<<1, 72>>>(gamma, beta, t);
    }
    k_precomp<<<161, 72>>>(W1, W2, b1, b2, mw1, mb1);
    k_uv<<<782, 288, SM_G2>>>();
    k_edge2<<<1480, EB>>>(ei, ea, mw2, mb2, out);
}